// round 1
// baseline (speedup 1.0000x reference)
#include <cuda_runtime.h>
#include <cuda_bf16.h>
#include <math.h>

// Scratch accumulator lives in a __device__ global (no allocations allowed).
__device__ double g_acc;

__global__ void nll_zero_kernel() {
    g_acc = 0.0;
}

// Grid-stride masked-NLL partial sum.
// pred: (B*G, 8) fp32, we read channel 0 -> stride-8 floats (one 32B sector each).
// mask: (B*G,) bool stored as 1 byte.
__global__ void __launch_bounds__(256) nll_main_kernel(
    const float* __restrict__ pred,
    const unsigned char* __restrict__ mask,
    int n)
{
    int tid = blockIdx.x * blockDim.x + threadIdx.x;
    int stride = gridDim.x * blockDim.x;

    float s = 0.0f;

    // Grid-stride loop; unroll to get several independent LDGs in flight (MLP).
    #pragma unroll 4
    for (int i = tid; i < n; i += stride) {
        float p = __ldg(&pred[(size_t)i * 8]);
        unsigned char m = __ldg(&mask[i]);
        // log(p) if masked, log1p(-p) otherwise. log1pf keeps the p->1 tail
        // accurate (matches jnp.log1p), avoiding systematic bias in the sum.
        s += m ? logf(p) : log1pf(-p);
    }

    // Warp reduction.
    #pragma unroll
    for (int o = 16; o > 0; o >>= 1)
        s += __shfl_xor_sync(0xFFFFFFFFu, s, o);

    // Block reduction via shared memory (one value per warp).
    __shared__ float warp_sums[8];  // 256 threads / 32
    int lane = threadIdx.x & 31;
    int warp = threadIdx.x >> 5;
    if (lane == 0) warp_sums[warp] = s;
    __syncthreads();

    if (warp == 0) {
        float bs = (lane < (blockDim.x >> 5)) ? warp_sums[lane] : 0.0f;
        #pragma unroll
        for (int o = 4; o > 0; o >>= 1)
            bs += __shfl_xor_sync(0xFFFFFFFFu, bs, o);
        if (lane == 0)
            atomicAdd(&g_acc, (double)bs);
    }
}

__global__ void nll_final_kernel(float* __restrict__ out, float inv_batch) {
    out[0] = (float)(-g_acc) * inv_batch;
}

extern "C" void kernel_launch(void* const* d_in, const int* in_sizes, int n_in,
                              void* d_out, int out_size)
{
    const float* pred = (const float*)d_in[0];          // (256, 16384, 8) fp32
    const unsigned char* mask = (const unsigned char*)d_in[1];  // (256, 16384) bool
    float* out = (float*)d_out;

    int n = in_sizes[1];            // B*G = 4,194,304 elements
    const float inv_batch = 1.0f / 256.0f;

    nll_zero_kernel<<<1, 1>>>();

    // ~16 blocks per SM wave-equivalent; 2368 blocks x 256 thr = 606K threads,
    // ~7 elements per thread -> plenty of in-flight sectors for HBM.
    int blocks = 148 * 16;
    nll_main_kernel<<<blocks, 256>>>(pred, mask, n);

    nll_final_kernel<<<1, 1>>>(out, inv_batch);
}